// round 3
// baseline (speedup 1.0000x reference)
#include <cuda_runtime.h>
#include <math.h>

#define DIM    512
#define NNEUR  4096
#define BT     8192   // B*T = 4*2048

// ---- scratch (device globals: allocation-free per harness rules) ----
__device__ float g_values[NNEUR * DIM];            // 8 MB
__device__ float g_p2[NNEUR];
__device__ float g_x2[BT];
__device__ float g_inter[(size_t)BT * NNEUR];      // 128 MB (interactions -> attn in place)
__device__ float g_mid[BT * DIM];                  // 16 MB

// ---------------------------------------------------------------------------
// row-wise sum of squares: one block (128 threads) per row of length DIM=512
// ---------------------------------------------------------------------------
__global__ void rowsumsq_kernel(const float* __restrict__ A, float* __restrict__ out) {
    const int row = blockIdx.x;
    const float4 v = reinterpret_cast<const float4*>(A + (size_t)row * DIM)[threadIdx.x];
    float s = v.x * v.x + v.y * v.y + v.z * v.z + v.w * v.w;
#pragma unroll
    for (int off = 16; off > 0; off >>= 1)
        s += __shfl_down_sync(0xffffffffu, s, off);
    __shared__ float ws[4];
    if ((threadIdx.x & 31) == 0) ws[threadIdx.x >> 5] = s;
    __syncthreads();
    if (threadIdx.x == 0) out[row] = ws[0] + ws[1] + ws[2] + ws[3];
}

// ---------------------------------------------------------------------------
// row softmax over NNEUR=4096, one block (256 threads) per row, in place
// ---------------------------------------------------------------------------
__global__ void softmax_kernel(float* __restrict__ data) {
    const int row = blockIdx.x;
    float4* p = reinterpret_cast<float4*>(data + (size_t)row * NNEUR);
    const int tid = threadIdx.x;
    float4 v[4];
    float mx = -1e30f;
#pragma unroll
    for (int i = 0; i < 4; i++) {
        v[i] = p[tid + i * 256];
        mx = fmaxf(mx, fmaxf(fmaxf(v[i].x, v[i].y), fmaxf(v[i].z, v[i].w)));
    }
    __shared__ float red[8];
#pragma unroll
    for (int off = 16; off > 0; off >>= 1)
        mx = fmaxf(mx, __shfl_xor_sync(0xffffffffu, mx, off));
    if ((tid & 31) == 0) red[tid >> 5] = mx;
    __syncthreads();
    mx = red[0];
#pragma unroll
    for (int w = 1; w < 8; w++) mx = fmaxf(mx, red[w]);

    float s = 0.f;
#pragma unroll
    for (int i = 0; i < 4; i++) {
        v[i].x = __expf(v[i].x - mx);
        v[i].y = __expf(v[i].y - mx);
        v[i].z = __expf(v[i].z - mx);
        v[i].w = __expf(v[i].w - mx);
        s += v[i].x + v[i].y + v[i].z + v[i].w;
    }
#pragma unroll
    for (int off = 16; off > 0; off >>= 1)
        s += __shfl_xor_sync(0xffffffffu, s, off);
    __syncthreads();                 // protect red[] reuse
    if ((tid & 31) == 0) red[tid >> 5] = s;
    __syncthreads();
    s = red[0] + red[1] + red[2] + red[3] + red[4] + red[5] + red[6] + red[7];
    const float inv = 1.0f / s;
#pragma unroll
    for (int i = 0; i < 4; i++) {
        v[i].x *= inv; v[i].y *= inv; v[i].z *= inv; v[i].w *= inv;
        p[tid + i * 256] = v[i];
    }
}

// ---------------------------------------------------------------------------
// 128x128x16 tiled fp32 GEMM, 8x8 per thread, 256 threads.
// BMODE: 0 = NN (B is K x Ncols, row-major), 1 = NT (B is Ncols x K, row-major)
// EPI:   0 = none, 1 = +bias[n], 2 = interaction transform
// All dims assumed multiples of 128 (true for this problem).
// ---------------------------------------------------------------------------
#define EPI_NONE  0
#define EPI_BIAS  1
#define EPI_INTER 2

template <int BMODE, int EPI>
__global__ __launch_bounds__(256) void gemm128(
    const float* __restrict__ A, const float* __restrict__ B, float* __restrict__ C,
    int M, int Ncols, int K,
    const float* __restrict__ bias,
    const float* __restrict__ x2, const float* __restrict__ p2,
    const float* __restrict__ scale)
{
    constexpr int BM = 128, BN = 128, BK = 16;
    __shared__ float As[BK][BM];
    __shared__ float Bs[BK][BN];

    const int tid = threadIdx.x;
    const int bm = blockIdx.y * BM;
    const int bn = blockIdx.x * BN;
    const int tr = tid >> 4;          // 0..15
    const int tc = tid & 15;          // 0..15
    const int m0 = tr * 8;
    const int n0 = tc * 8;

    float acc[8][8] = {};

    for (int k0 = 0; k0 < K; k0 += BK) {
        // ---- load A tile: 128 rows x 16 cols (K-contiguous) ----
#pragma unroll
        for (int i = 0; i < 2; i++) {
            const int idx = tid + i * 256;       // 0..511
            const int row = idx >> 2;            // 0..127
            const int c4  = idx & 3;             // 0..3
            const float4 v = *reinterpret_cast<const float4*>(
                &A[(size_t)(bm + row) * K + k0 + c4 * 4]);
            As[c4 * 4 + 0][row] = v.x;
            As[c4 * 4 + 1][row] = v.y;
            As[c4 * 4 + 2][row] = v.z;
            As[c4 * 4 + 3][row] = v.w;
        }
        // ---- load B tile ----
        if (BMODE == 1) {   // NT: B is Ncols x K
#pragma unroll
            for (int i = 0; i < 2; i++) {
                const int idx = tid + i * 256;
                const int row = idx >> 2;
                const int c4  = idx & 3;
                const float4 v = *reinterpret_cast<const float4*>(
                    &B[(size_t)(bn + row) * K + k0 + c4 * 4]);
                Bs[c4 * 4 + 0][row] = v.x;
                Bs[c4 * 4 + 1][row] = v.y;
                Bs[c4 * 4 + 2][row] = v.z;
                Bs[c4 * 4 + 3][row] = v.w;
            }
        } else {            // NN: B is K x Ncols
#pragma unroll
            for (int i = 0; i < 2; i++) {
                const int idx = tid + i * 256;   // 0..511
                const int kr = idx >> 5;         // 0..15
                const int c4 = idx & 31;         // 0..31
                const float4 v = *reinterpret_cast<const float4*>(
                    &B[(size_t)(k0 + kr) * Ncols + bn + c4 * 4]);
                *reinterpret_cast<float4*>(&Bs[kr][c4 * 4]) = v;
            }
        }
        __syncthreads();

        // ---- compute ----
#pragma unroll
        for (int k = 0; k < BK; k++) {
            float a[8], b[8];
            *reinterpret_cast<float4*>(&a[0]) = *reinterpret_cast<float4*>(&As[k][m0]);
            *reinterpret_cast<float4*>(&a[4]) = *reinterpret_cast<float4*>(&As[k][m0 + 4]);
            *reinterpret_cast<float4*>(&b[0]) = *reinterpret_cast<float4*>(&Bs[k][n0]);
            *reinterpret_cast<float4*>(&b[4]) = *reinterpret_cast<float4*>(&Bs[k][n0 + 4]);
#pragma unroll
            for (int i = 0; i < 8; i++)
#pragma unroll
                for (int j = 0; j < 8; j++)
                    acc[i][j] = fmaf(a[i], b[j], acc[i][j]);
        }
        __syncthreads();
    }

    // ---- epilogue ----
    if (EPI == EPI_INTER) {
        float p2v[8], scv[8];
#pragma unroll
        for (int j = 0; j < 8; j++) {
            p2v[j] = p2[bn + n0 + j];
            scv[j] = scale[bn + n0 + j];
        }
#pragma unroll
        for (int i = 0; i < 8; i++) {
            const float x2v = x2[bm + m0 + i];
#pragma unroll
            for (int j = 0; j < 8; j++) {
                const float sq = fmaxf(x2v - 2.0f * acc[i][j] + p2v[j], 0.0f);
                acc[i][j] = scv[j] / (sqrtf(sq) + 0.1f);
            }
        }
    } else if (EPI == EPI_BIAS) {
        float bv[8];
#pragma unroll
        for (int j = 0; j < 8; j++) bv[j] = bias[bn + n0 + j];
#pragma unroll
        for (int i = 0; i < 8; i++)
#pragma unroll
            for (int j = 0; j < 8; j++) acc[i][j] += bv[j];
    }

#pragma unroll
    for (int i = 0; i < 8; i++) {
        const size_t base = (size_t)(bm + m0 + i) * Ncols + bn + n0;
        *reinterpret_cast<float4*>(&C[base]) =
            make_float4(acc[i][0], acc[i][1], acc[i][2], acc[i][3]);
        *reinterpret_cast<float4*>(&C[base + 4]) =
            make_float4(acc[i][4], acc[i][5], acc[i][6], acc[i][7]);
    }
}

// ---------------------------------------------------------------------------
extern "C" void kernel_launch(void* const* d_in, const int* in_sizes, int n_in,
                              void* d_out, int out_size)
{
    const float* x     = (const float*)d_in[0];   // (B,T,D)     8192x512
    const float* pos   = (const float*)d_in[1];   // (N,D)       4096x512
    const float* scale = (const float*)d_in[2];   // (N,)
    const float* w_v   = (const float*)d_in[3];   // (D,D)
    const float* b_v   = (const float*)d_in[4];   // (D,)
    const float* w_o   = (const float*)d_in[5];   // (D,D)
    const float* b_o   = (const float*)d_in[6];   // (D,)
    float* out = (float*)d_out;                   // (B,T,D)

    // Resolve scratch symbol addresses once (deterministic; keeps the capture
    // call to pure kernel launches).
    static float *pv = nullptr, *pp2, *px2, *pinter, *pmid;
    if (pv == nullptr) {
        cudaGetSymbolAddress((void**)&pv,     g_values);
        cudaGetSymbolAddress((void**)&pp2,    g_p2);
        cudaGetSymbolAddress((void**)&px2,    g_x2);
        cudaGetSymbolAddress((void**)&pinter, g_inter);
        cudaGetSymbolAddress((void**)&pmid,   g_mid);
    }

    // norms
    rowsumsq_kernel<<<BT,    128>>>(x,   px2);
    rowsumsq_kernel<<<NNEUR, 128>>>(pos, pp2);

    // values = positions @ w_v^T + b_v        (4096 x 512, K=512, NT)
    gemm128<1, EPI_BIAS><<<dim3(DIM / 128, NNEUR / 128), 256>>>(
        pos, w_v, pv, NNEUR, DIM, DIM, b_v, nullptr, nullptr, nullptr);

    // interactions = f(x @ positions^T)       (8192 x 4096, K=512, NT + epilogue)
    gemm128<1, EPI_INTER><<<dim3(NNEUR / 128, BT / 128), 256>>>(
        x, pos, pinter, BT, NNEUR, DIM, nullptr, px2, pp2, scale);

    // softmax over neurons (in place)
    softmax_kernel<<<BT, 256>>>(pinter);

    // mid = attn @ values                     (8192 x 512, K=4096, NN)
    gemm128<0, EPI_NONE><<<dim3(DIM / 128, BT / 128), 256>>>(
        pinter, pv, pmid, BT, DIM, NNEUR, nullptr, nullptr, nullptr, nullptr);

    // out = mid @ w_o^T + b_o                 (8192 x 512, K=512, NT)
    gemm128<1, EPI_BIAS><<<dim3(DIM / 128, BT / 128), 256>>>(
        pmid, w_o, out, BT, DIM, DIM, b_o, nullptr, nullptr, nullptr);
}

// round 5
// speedup vs baseline: 3.7492x; 3.7492x over previous
#include <cuda_runtime.h>
#include <cuda_bf16.h>
#include <math.h>
#include <stdint.h>

#define DIM    512
#define NNEUR  4096
#define BT     8192   // B*T

// ---------------- scratch (device globals; allocation-free) ----------------
__device__ __align__(16) float         g_values[NNEUR * DIM];          // 8 MB fp32
__device__ __align__(16) float         g_mid[BT * DIM];                // 16 MB fp32
__device__ float                       g_p2[NNEUR];
__device__ float                       g_x2[BT];
__device__ __align__(16) __nv_bfloat16 g_xb[BT * DIM];                 // 8 MB
__device__ __align__(16) __nv_bfloat16 g_pb[NNEUR * DIM];              // 4 MB
__device__ __align__(16) __nv_bfloat16 g_vT[DIM * NNEUR];              // 4 MB (values^T)
__device__ __align__(16) __nv_bfloat16 g_attn[(size_t)BT * NNEUR];     // 64 MB

// ---------------- warp-mma helpers (base ISA: sm_80+, no 'a' suffix) -------
__device__ __forceinline__ uint32_t smem_to_u32(const void* p) {
    uint32_t a;
    asm("{ .reg .u64 t; cvta.to.shared.u64 t, %1; cvt.u32.u64 %0, t; }" : "=r"(a) : "l"(p));
    return a;
}
__device__ __forceinline__ void ldsm4(uint32_t& r0, uint32_t& r1, uint32_t& r2,
                                      uint32_t& r3, uint32_t addr) {
    asm volatile("ldmatrix.sync.aligned.m8n8.x4.shared.b16 {%0,%1,%2,%3}, [%4];"
                 : "=r"(r0), "=r"(r1), "=r"(r2), "=r"(r3) : "r"(addr));
}
__device__ __forceinline__ void mma16816(float* c, const uint32_t* a,
                                         uint32_t b0, uint32_t b1) {
    asm volatile(
        "mma.sync.aligned.m16n8k16.row.col.f32.bf16.bf16.f32 "
        "{%0,%1,%2,%3}, {%4,%5,%6,%7}, {%8,%9}, {%0,%1,%2,%3};"
        : "+f"(c[0]), "+f"(c[1]), "+f"(c[2]), "+f"(c[3])
        : "r"(a[0]), "r"(a[1]), "r"(a[2]), "r"(a[3]), "r"(b0), "r"(b1));
}

// swizzled smem offset for 64B rows (4 x 16B chunks), conflict-free ldmatrix
__device__ __forceinline__ uint32_t swz_off(int row, int chunk) {
    return (uint32_t)(row * 64 + ((chunk ^ ((row >> 1) & 3)) << 4));
}

// ---------------------------------------------------------------------------
// mma_gemm: C[M,N] = A[M,K] @ B[N,K]^T, bf16 in, fp32 acc.
// BM=128, BN=128, BK=32, 256 threads = 8 warps (2 m x 4 n), warp tile 64x32.
// EPI 0: store fp32.  EPI 1: interaction transform, store bf16.
// ---------------------------------------------------------------------------
template <int EPI>
__global__ __launch_bounds__(256) void mma_gemm(
    const __nv_bfloat16* __restrict__ A, const __nv_bfloat16* __restrict__ B,
    void* __restrict__ Cv, int ldA, int ldB, int ldC, int niter,
    const float* __restrict__ x2, const float* __restrict__ p2,
    const float* __restrict__ scale)
{
    __shared__ __align__(128) __nv_bfloat16 As[2][128 * 32];
    __shared__ __align__(128) __nv_bfloat16 Bs[2][128 * 32];
    __shared__ float p2s[128], scs[128];

    const int tid  = threadIdx.x;
    const int lane = tid & 31, wid = tid >> 5;
    const int warp_m = wid >> 2, warp_n = wid & 3;     // 2 x 4
    const int bm = blockIdx.y * 128, bn = blockIdx.x * 128;

    if (EPI == 1 && tid < 128) {
        p2s[tid] = p2[bn + tid];
        scs[tid] = scale[bn + tid];
    }

    const int lrow = tid >> 2;          // 0..63  (loader: 2 rows per thread)
    const int lchk = tid & 3;           // 0..3

    // stage-0 load
    {
        char* a0 = reinterpret_cast<char*>(As[0]);
        char* b0 = reinterpret_cast<char*>(Bs[0]);
#pragma unroll
        for (int h = 0; h < 2; h++) {
            const int r = lrow + h * 64;
            *reinterpret_cast<uint4*>(a0 + swz_off(r, lchk)) =
                *reinterpret_cast<const uint4*>(A + (size_t)(bm + r) * ldA + lchk * 8);
            *reinterpret_cast<uint4*>(b0 + swz_off(r, lchk)) =
                *reinterpret_cast<const uint4*>(B + (size_t)(bn + r) * ldB + lchk * 8);
        }
    }
    __syncthreads();

    float acc[4][4][4] = {};
    const int rin = lane & 7, matid = lane >> 3;

    for (int it = 0; it < niter; it++) {
        const int st = it & 1;
        // prefetch next tile into the other stage
        if (it + 1 < niter) {
            const int k0 = (it + 1) * 32;
            char* an = reinterpret_cast<char*>(As[st ^ 1]);
            char* bnx = reinterpret_cast<char*>(Bs[st ^ 1]);
#pragma unroll
            for (int h = 0; h < 2; h++) {
                const int r = lrow + h * 64;
                *reinterpret_cast<uint4*>(an + swz_off(r, lchk)) =
                    *reinterpret_cast<const uint4*>(A + (size_t)(bm + r) * ldA + k0 + lchk * 8);
                *reinterpret_cast<uint4*>(bnx + swz_off(r, lchk)) =
                    *reinterpret_cast<const uint4*>(B + (size_t)(bn + r) * ldB + k0 + lchk * 8);
            }
        }
        const uint32_t a_s = smem_to_u32(As[st]);
        const uint32_t b_s = smem_to_u32(Bs[st]);
#pragma unroll
        for (int s = 0; s < 2; s++) {                  // two k16 steps per BK=32
            uint32_t af[4][4], bf[2][4];
#pragma unroll
            for (int mb = 0; mb < 4; mb++) {
                const int row = warp_m * 64 + mb * 16 + (matid & 1) * 8 + rin;
                const int chk = s * 2 + (matid >> 1);
                ldsm4(af[mb][0], af[mb][1], af[mb][2], af[mb][3], a_s + swz_off(row, chk));
            }
#pragma unroll
            for (int nb2 = 0; nb2 < 2; nb2++) {
                const int row = warp_n * 32 + nb2 * 16 + (matid >> 1) * 8 + rin;
                const int chk = s * 2 + (matid & 1);
                ldsm4(bf[nb2][0], bf[nb2][1], bf[nb2][2], bf[nb2][3], b_s + swz_off(row, chk));
            }
#pragma unroll
            for (int mb = 0; mb < 4; mb++)
#pragma unroll
                for (int nb = 0; nb < 4; nb++)
                    mma16816(acc[mb][nb], af[mb],
                             bf[nb >> 1][(nb & 1) * 2], bf[nb >> 1][(nb & 1) * 2 + 1]);
        }
        __syncthreads();
    }

    // ---- epilogue ----
    const int g = lane >> 2, tig = lane & 3;
#pragma unroll
    for (int mb = 0; mb < 4; mb++) {
        const int r0 = warp_m * 64 + mb * 16 + g;      // local rows r0, r0+8
        float xa = 0.f, xb = 0.f;
        if (EPI == 1) { xa = x2[bm + r0]; xb = x2[bm + r0 + 8]; }
#pragma unroll
        for (int nb = 0; nb < 4; nb++) {
            const int cl = warp_n * 32 + nb * 8 + 2 * tig;   // local col (even)
            const float* c = acc[mb][nb];
            if (EPI == 1) {
                const float p0 = p2s[cl], p1 = p2s[cl + 1];
                const float s0 = scs[cl], s1 = scs[cl + 1];
                float q0 = fmaxf(xa - 2.f * c[0] + p0, 0.f);
                float q1 = fmaxf(xa - 2.f * c[1] + p1, 0.f);
                float q2 = fmaxf(xb - 2.f * c[2] + p0, 0.f);
                float q3 = fmaxf(xb - 2.f * c[3] + p1, 0.f);
                __nv_bfloat16* Cb = reinterpret_cast<__nv_bfloat16*>(Cv);
                *reinterpret_cast<__nv_bfloat162*>(Cb + (size_t)(bm + r0) * ldC + bn + cl) =
                    __floats2bfloat162_rn(s0 / (sqrtf(q0) + 0.1f), s1 / (sqrtf(q1) + 0.1f));
                *reinterpret_cast<__nv_bfloat162*>(Cb + (size_t)(bm + r0 + 8) * ldC + bn + cl) =
                    __floats2bfloat162_rn(s0 / (sqrtf(q2) + 0.1f), s1 / (sqrtf(q3) + 0.1f));
            } else {
                float* Cf = reinterpret_cast<float*>(Cv);
                *reinterpret_cast<float2*>(Cf + (size_t)(bm + r0) * ldC + bn + cl) =
                    make_float2(c[0], c[1]);
                *reinterpret_cast<float2*>(Cf + (size_t)(bm + r0 + 8) * ldC + bn + cl) =
                    make_float2(c[2], c[3]);
            }
        }
    }
}

// ---------------------------------------------------------------------------
// fp32 convert + row sum-of-squares (1 block / row, 128 thr)
// ---------------------------------------------------------------------------
__global__ void conv_rowsq(const float* __restrict__ A, __nv_bfloat16* __restrict__ Ab,
                           float* __restrict__ out) {
    const int row = blockIdx.x;
    const int tid = threadIdx.x;
    const float4 v = reinterpret_cast<const float4*>(A + (size_t)row * DIM)[tid];
    float s = v.x * v.x + v.y * v.y + v.z * v.z + v.w * v.w;
    union { uint2 u; __nv_bfloat162 h[2]; } w;
    w.h[0] = __floats2bfloat162_rn(v.x, v.y);
    w.h[1] = __floats2bfloat162_rn(v.z, v.w);
    reinterpret_cast<uint2*>(Ab + (size_t)row * DIM)[tid] = w.u;
#pragma unroll
    for (int off = 16; off > 0; off >>= 1) s += __shfl_down_sync(0xffffffffu, s, off);
    __shared__ float ws[4];
    if ((tid & 31) == 0) ws[tid >> 5] = s;
    __syncthreads();
    if (tid == 0) out[row] = ws[0] + ws[1] + ws[2] + ws[3];
}

// values [N][D] fp32 -> valuesT [D][N] bf16  (32x32 tiles, block (32,8))
__global__ void transp_conv(const float* __restrict__ V, __nv_bfloat16* __restrict__ VT) {
    __shared__ float t[32][33];
    const int d0 = blockIdx.x * 32, n0 = blockIdx.y * 32;
    const int tx = threadIdx.x, ty = threadIdx.y;
#pragma unroll
    for (int i = 0; i < 4; i++)
        t[ty + 8 * i][tx] = V[(size_t)(n0 + ty + 8 * i) * DIM + d0 + tx];
    __syncthreads();
#pragma unroll
    for (int i = 0; i < 4; i++)
        VT[(size_t)(d0 + ty + 8 * i) * NNEUR + n0 + tx] = __float2bfloat16(t[tx][ty + 8 * i]);
}

// ---------------------------------------------------------------------------
// row softmax over 4096 bf16, in place (fp32 math), 1 block / row, 256 thr
// ---------------------------------------------------------------------------
__global__ __launch_bounds__(256) void softmax_bf16(__nv_bfloat16* __restrict__ data) {
    const int row = blockIdx.x;
    const int tid = threadIdx.x;
    uint4* p = reinterpret_cast<uint4*>(data + (size_t)row * NNEUR);
    uint4 a = p[tid], b = p[tid + 256];
    float f[16];
    const __nv_bfloat162* ha = reinterpret_cast<const __nv_bfloat162*>(&a);
    const __nv_bfloat162* hb = reinterpret_cast<const __nv_bfloat162*>(&b);
#pragma unroll
    for (int i = 0; i < 4; i++) {
        float2 u = __bfloat1622float2(ha[i]);
        f[2 * i] = u.x; f[2 * i + 1] = u.y;
        float2 w = __bfloat1622float2(hb[i]);
        f[8 + 2 * i] = w.x; f[8 + 2 * i + 1] = w.y;
    }
    float mx = f[0];
#pragma unroll
    for (int i = 1; i < 16; i++) mx = fmaxf(mx, f[i]);
    __shared__ float red[8];
#pragma unroll
    for (int off = 16; off > 0; off >>= 1)
        mx = fmaxf(mx, __shfl_xor_sync(0xffffffffu, mx, off));
    if ((tid & 31) == 0) red[tid >> 5] = mx;
    __syncthreads();
    mx = red[0];
#pragma unroll
    for (int w = 1; w < 8; w++) mx = fmaxf(mx, red[w]);

    float s = 0.f;
#pragma unroll
    for (int i = 0; i < 16; i++) { f[i] = __expf(f[i] - mx); s += f[i]; }
#pragma unroll
    for (int off = 16; off > 0; off >>= 1) s += __shfl_xor_sync(0xffffffffu, s, off);
    __syncthreads();
    if ((tid & 31) == 0) red[tid >> 5] = s;
    __syncthreads();
    s = red[0] + red[1] + red[2] + red[3] + red[4] + red[5] + red[6] + red[7];
    const float inv = 1.0f / s;

    __nv_bfloat162* oa = reinterpret_cast<__nv_bfloat162*>(&a);
    __nv_bfloat162* ob = reinterpret_cast<__nv_bfloat162*>(&b);
#pragma unroll
    for (int i = 0; i < 4; i++) {
        oa[i] = __floats2bfloat162_rn(f[2 * i] * inv, f[2 * i + 1] * inv);
        ob[i] = __floats2bfloat162_rn(f[8 + 2 * i] * inv, f[8 + 2 * i + 1] * inv);
    }
    p[tid] = a;
    p[tid + 256] = b;
}

// ---------------------------------------------------------------------------
// fp32 SIMT GEMM (precision-sensitive small GEMMs): NT + bias
// ---------------------------------------------------------------------------
__global__ __launch_bounds__(256) void gemm_nt_bias(
    const float* __restrict__ A, const float* __restrict__ B, float* __restrict__ C,
    int Ncols, int K, const float* __restrict__ bias)
{
    constexpr int BK = 16;
    __shared__ float As[BK][128];
    __shared__ float Bs[BK][128];
    const int tid = threadIdx.x;
    const int bm = blockIdx.y * 128, bn = blockIdx.x * 128;
    const int m0 = (tid >> 4) * 8, n0 = (tid & 15) * 8;
    float acc[8][8] = {};

    for (int k0 = 0; k0 < K; k0 += BK) {
#pragma unroll
        for (int i = 0; i < 2; i++) {
            const int idx = tid + i * 256;
            const int row = idx >> 2, c4 = idx & 3;
            float4 v = *reinterpret_cast<const float4*>(&A[(size_t)(bm + row) * K + k0 + c4 * 4]);
            As[c4 * 4 + 0][row] = v.x; As[c4 * 4 + 1][row] = v.y;
            As[c4 * 4 + 2][row] = v.z; As[c4 * 4 + 3][row] = v.w;
            v = *reinterpret_cast<const float4*>(&B[(size_t)(bn + row) * K + k0 + c4 * 4]);
            Bs[c4 * 4 + 0][row] = v.x; Bs[c4 * 4 + 1][row] = v.y;
            Bs[c4 * 4 + 2][row] = v.z; Bs[c4 * 4 + 3][row] = v.w;
        }
        __syncthreads();
#pragma unroll
        for (int k = 0; k < BK; k++) {
            float a[8], b[8];
            *reinterpret_cast<float4*>(&a[0]) = *reinterpret_cast<float4*>(&As[k][m0]);
            *reinterpret_cast<float4*>(&a[4]) = *reinterpret_cast<float4*>(&As[k][m0 + 4]);
            *reinterpret_cast<float4*>(&b[0]) = *reinterpret_cast<float4*>(&Bs[k][n0]);
            *reinterpret_cast<float4*>(&b[4]) = *reinterpret_cast<float4*>(&Bs[k][n0 + 4]);
#pragma unroll
            for (int i = 0; i < 8; i++)
#pragma unroll
                for (int j = 0; j < 8; j++) acc[i][j] = fmaf(a[i], b[j], acc[i][j]);
        }
        __syncthreads();
    }
    float bv[8];
#pragma unroll
    for (int j = 0; j < 8; j++) bv[j] = bias[bn + n0 + j];
#pragma unroll
    for (int i = 0; i < 8; i++) {
        const size_t base = (size_t)(bm + m0 + i) * Ncols + bn + n0;
        *reinterpret_cast<float4*>(&C[base]) =
            make_float4(acc[i][0] + bv[0], acc[i][1] + bv[1], acc[i][2] + bv[2], acc[i][3] + bv[3]);
        *reinterpret_cast<float4*>(&C[base + 4]) =
            make_float4(acc[i][4] + bv[4], acc[i][5] + bv[5], acc[i][6] + bv[6], acc[i][7] + bv[7]);
    }
}

// ---------------------------------------------------------------------------
extern "C" void kernel_launch(void* const* d_in, const int* in_sizes, int n_in,
                              void* d_out, int out_size)
{
    const float* x     = (const float*)d_in[0];
    const float* pos   = (const float*)d_in[1];
    const float* scale = (const float*)d_in[2];
    const float* w_v   = (const float*)d_in[3];
    const float* b_v   = (const float*)d_in[4];
    const float* w_o   = (const float*)d_in[5];
    const float* b_o   = (const float*)d_in[6];
    float* out = (float*)d_out;

    static float* pv = nullptr;
    static float *pmid, *pp2, *px2;
    static __nv_bfloat16 *pxb, *ppb, *pvT, *pattn;
    if (pv == nullptr) {
        cudaGetSymbolAddress((void**)&pv,    g_values);
        cudaGetSymbolAddress((void**)&pmid,  g_mid);
        cudaGetSymbolAddress((void**)&pp2,   g_p2);
        cudaGetSymbolAddress((void**)&px2,   g_x2);
        cudaGetSymbolAddress((void**)&pxb,   g_xb);
        cudaGetSymbolAddress((void**)&ppb,   g_pb);
        cudaGetSymbolAddress((void**)&pvT,   g_vT);
        cudaGetSymbolAddress((void**)&pattn, g_attn);
    }

    // converts + norms
    conv_rowsq<<<BT,    128>>>(x,   pxb, px2);
    conv_rowsq<<<NNEUR, 128>>>(pos, ppb, pp2);

    // values = positions @ w_v^T + b_v   (fp32, precision-sensitive)
    gemm_nt_bias<<<dim3(DIM / 128, NNEUR / 128), 256>>>(pos, w_v, pv, DIM, DIM, b_v);
    transp_conv<<<dim3(DIM / 32, NNEUR / 32), dim3(32, 8)>>>(pv, pvT);

    // interactions = f(x @ positions^T)  (bf16 HMMA, fused epilogue, bf16 out)
    mma_gemm<1><<<dim3(NNEUR / 128, BT / 128), 256>>>(
        pxb, ppb, pattn, DIM, DIM, NNEUR, DIM / 32, px2, pp2, scale);

    // softmax over neurons (bf16 in/out, fp32 math)
    softmax_bf16<<<BT, 256>>>(pattn);

    // mid = attn @ values                (bf16 HMMA, fp32 out)
    mma_gemm<0><<<dim3(DIM / 128, BT / 128), 256>>>(
        pattn, pvT, pmid, NNEUR, NNEUR, DIM, NNEUR / 32, nullptr, nullptr, nullptr);

    // out = mid @ w_o^T + b_o            (fp32, precision-sensitive)
    gemm_nt_bias<<<dim3(DIM / 128, BT / 128), 256>>>(pmid, w_o, out, DIM, DIM, b_o);
}

// round 6
// speedup vs baseline: 6.3976x; 1.7064x over previous
#include <cuda_runtime.h>
#include <cuda_bf16.h>
#include <math.h>
#include <stdint.h>

#define DIM    512
#define NNEUR  4096
#define BT     8192   // B*T

// ---------------- scratch (device globals; allocation-free) ----------------
__device__ float                       g_p2[NNEUR];
__device__ float                       g_x2[BT];
__device__ float                       g_cvec[DIM];
__device__ __align__(16) __nv_bfloat16 g_xb[BT * DIM];                 // 8 MB
__device__ __align__(16) __nv_bfloat16 g_pb[NNEUR * DIM];              // 4 MB
__device__ __align__(16) __nv_bfloat16 g_wvb[DIM * DIM];               // 0.5 MB
__device__ __align__(16) __nv_bfloat16 g_wob[DIM * DIM];               // 0.5 MB
__device__ __align__(16) __nv_bfloat16 g_valb[NNEUR * DIM];            // 4 MB  values
__device__ __align__(16) __nv_bfloat16 g_w2b[DIM * NNEUR];             // 4 MB  W2^T
__device__ __align__(16) __nv_bfloat16 g_attn[(size_t)BT * NNEUR];     // 64 MB

// ---------------- warp-mma helpers (base ISA: sm_80+, no 'a' suffix) -------
__device__ __forceinline__ uint32_t smem_to_u32(const void* p) {
    uint32_t a;
    asm("{ .reg .u64 t; cvta.to.shared.u64 t, %1; cvt.u32.u64 %0, t; }" : "=r"(a) : "l"(p));
    return a;
}
__device__ __forceinline__ void ldsm4(uint32_t& r0, uint32_t& r1, uint32_t& r2,
                                      uint32_t& r3, uint32_t addr) {
    asm volatile("ldmatrix.sync.aligned.m8n8.x4.shared.b16 {%0,%1,%2,%3}, [%4];"
                 : "=r"(r0), "=r"(r1), "=r"(r2), "=r"(r3) : "r"(addr));
}
__device__ __forceinline__ void mma16816(float* c, const uint32_t* a,
                                         uint32_t b0, uint32_t b1) {
    asm volatile(
        "mma.sync.aligned.m16n8k16.row.col.f32.bf16.bf16.f32 "
        "{%0,%1,%2,%3}, {%4,%5,%6,%7}, {%8,%9}, {%0,%1,%2,%3};"
        : "+f"(c[0]), "+f"(c[1]), "+f"(c[2]), "+f"(c[3])
        : "r"(a[0]), "r"(a[1]), "r"(a[2]), "r"(a[3]), "r"(b0), "r"(b1));
}
__device__ __forceinline__ void cp16(uint32_t dst, const void* src) {
    asm volatile("cp.async.cg.shared.global [%0], [%1], 16;" :: "r"(dst), "l"(src));
}
#define CP_COMMIT() asm volatile("cp.async.commit_group;" ::: "memory")
#define CP_WAIT(n)  asm volatile("cp.async.wait_group %0;" :: "n"(n) : "memory")

// swizzled smem offset for 64B rows (4 x 16B chunks), conflict-free ldmatrix
__device__ __forceinline__ uint32_t swz_off(int row, int chunk) {
    return (uint32_t)(row * 64 + ((chunk ^ ((row >> 1) & 3)) << 4));
}

// ---------------------------------------------------------------------------
// mma_gemm: C[M,N] = A[M,K] @ B[N,K]^T, bf16 in, fp32 acc.
// BM=128, BN=128, BK=32, 256 threads = 8 warps (2 m x 4 n), warp tile 64x32.
// 3-stage cp.async pipeline (stage = 16 KB: A 8 KB + B 8 KB).
// EPI 0: fp32 store.  EPI 1: interaction -> bf16.  EPI 2: plain bf16.
// EPI 3: +bias[n] -> fp32.
// Requires niter >= 2.
// ---------------------------------------------------------------------------
static constexpr int MG_STAGES = 3;
static constexpr int MG_SMEM   = MG_STAGES * 16384;   // 48 KB dynamic

template <int EPI>
__global__ __launch_bounds__(256) void mma_gemm(
    const __nv_bfloat16* __restrict__ A, const __nv_bfloat16* __restrict__ B,
    void* __restrict__ Cv, int ldA, int ldB, int ldC, int niter,
    const float* __restrict__ x2, const float* __restrict__ p2,
    const float* __restrict__ scale)   // scale = bias vector for EPI 3
{
    extern __shared__ __align__(128) char dsm[];
    __shared__ float p2s[128], scs[128];

    const int tid  = threadIdx.x;
    const int lane = tid & 31, wid = tid >> 5;
    const int warp_m = wid >> 2, warp_n = wid & 3;     // 2 x 4
    const int bm = blockIdx.y * 128, bn = blockIdx.x * 128;

    if (EPI == 1 && tid < 128) {
        p2s[tid] = p2[bn + tid];
        scs[tid] = scale[bn + tid];
    }
    if (EPI == 3 && tid < 128) scs[tid] = scale[bn + tid];

    const int lrow = tid >> 2;          // 0..63  (2 rows per thread)
    const int lchk = tid & 3;           // 0..3
    const uint32_t su = smem_to_u32(dsm);

    auto issue = [&](int it) {
        const int slot = it % MG_STAGES;
        const int k0 = it * 32;
        const uint32_t ab = su + slot * 16384;
        const uint32_t bb = ab + 8192;
#pragma unroll
        for (int h = 0; h < 2; h++) {
            const int r = lrow + h * 64;
            cp16(ab + swz_off(r, lchk), A + (size_t)(bm + r) * ldA + k0 + lchk * 8);
            cp16(bb + swz_off(r, lchk), B + (size_t)(bn + r) * ldB + k0 + lchk * 8);
        }
        CP_COMMIT();
    };

    issue(0);
    issue(1);

    float acc[4][4][4] = {};
    const int rin = lane & 7, matid = lane >> 3;

    for (int it = 0; it < niter; it++) {
        if (it == niter - 1) CP_WAIT(0); else CP_WAIT(1);
        __syncthreads();                  // slot ready + all warps done w/ prior slot
        if (it + MG_STAGES - 1 < niter) issue(it + MG_STAGES - 1);

        const uint32_t a_s = su + (it % MG_STAGES) * 16384;
        const uint32_t b_s = a_s + 8192;
#pragma unroll
        for (int s = 0; s < 2; s++) {                  // two k16 steps per BK=32
            uint32_t af[4][4], bf[2][4];
#pragma unroll
            for (int mb = 0; mb < 4; mb++) {
                const int row = warp_m * 64 + mb * 16 + (matid & 1) * 8 + rin;
                const int chk = s * 2 + (matid >> 1);
                ldsm4(af[mb][0], af[mb][1], af[mb][2], af[mb][3], a_s + swz_off(row, chk));
            }
#pragma unroll
            for (int nb2 = 0; nb2 < 2; nb2++) {
                const int row = warp_n * 32 + nb2 * 16 + (matid >> 1) * 8 + rin;
                const int chk = s * 2 + (matid & 1);
                ldsm4(bf[nb2][0], bf[nb2][1], bf[nb2][2], bf[nb2][3], b_s + swz_off(row, chk));
            }
#pragma unroll
            for (int mb = 0; mb < 4; mb++)
#pragma unroll
                for (int nb = 0; nb < 4; nb++)
                    mma16816(acc[mb][nb], af[mb],
                             bf[nb >> 1][(nb & 1) * 2], bf[nb >> 1][(nb & 1) * 2 + 1]);
        }
    }

    // ---- epilogue ----
    const int g = lane >> 2, tig = lane & 3;
#pragma unroll
    for (int mb = 0; mb < 4; mb++) {
        const int r0 = warp_m * 64 + mb * 16 + g;      // local rows r0, r0+8
        float xa = 0.f, xb = 0.f;
        if (EPI == 1) { xa = x2[bm + r0]; xb = x2[bm + r0 + 8]; }
#pragma unroll
        for (int nb = 0; nb < 4; nb++) {
            const int cl = warp_n * 32 + nb * 8 + 2 * tig;   // local col (even)
            const float* c = acc[mb][nb];
            if (EPI == 1) {
                const float p0 = p2s[cl], p1 = p2s[cl + 1];
                const float s0 = scs[cl], s1 = scs[cl + 1];
                float q0 = fmaxf(xa - 2.f * c[0] + p0, 0.f);
                float q1 = fmaxf(xa - 2.f * c[1] + p1, 0.f);
                float q2 = fmaxf(xb - 2.f * c[2] + p0, 0.f);
                float q3 = fmaxf(xb - 2.f * c[3] + p1, 0.f);
                __nv_bfloat16* Cb = reinterpret_cast<__nv_bfloat16*>(Cv);
                *reinterpret_cast<__nv_bfloat162*>(Cb + (size_t)(bm + r0) * ldC + bn + cl) =
                    __floats2bfloat162_rn(s0 / (sqrtf(q0) + 0.1f), s1 / (sqrtf(q1) + 0.1f));
                *reinterpret_cast<__nv_bfloat162*>(Cb + (size_t)(bm + r0 + 8) * ldC + bn + cl) =
                    __floats2bfloat162_rn(s0 / (sqrtf(q2) + 0.1f), s1 / (sqrtf(q3) + 0.1f));
            } else if (EPI == 2) {
                __nv_bfloat16* Cb = reinterpret_cast<__nv_bfloat16*>(Cv);
                *reinterpret_cast<__nv_bfloat162*>(Cb + (size_t)(bm + r0) * ldC + bn + cl) =
                    __floats2bfloat162_rn(c[0], c[1]);
                *reinterpret_cast<__nv_bfloat162*>(Cb + (size_t)(bm + r0 + 8) * ldC + bn + cl) =
                    __floats2bfloat162_rn(c[2], c[3]);
            } else if (EPI == 3) {
                const float b0 = scs[cl], b1 = scs[cl + 1];
                float* Cf = reinterpret_cast<float*>(Cv);
                *reinterpret_cast<float2*>(Cf + (size_t)(bm + r0) * ldC + bn + cl) =
                    make_float2(c[0] + b0, c[1] + b1);
                *reinterpret_cast<float2*>(Cf + (size_t)(bm + r0 + 8) * ldC + bn + cl) =
                    make_float2(c[2] + b0, c[3] + b1);
            } else {
                float* Cf = reinterpret_cast<float*>(Cv);
                *reinterpret_cast<float2*>(Cf + (size_t)(bm + r0) * ldC + bn + cl) =
                    make_float2(c[0], c[1]);
                *reinterpret_cast<float2*>(Cf + (size_t)(bm + r0 + 8) * ldC + bn + cl) =
                    make_float2(c[2], c[3]);
            }
        }
    }
}

// ---------------------------------------------------------------------------
// fp32 convert + row sum-of-squares (1 block / row of DIM, 128 thr)
// ---------------------------------------------------------------------------
__global__ void conv_rowsq(const float* __restrict__ A, __nv_bfloat16* __restrict__ Ab,
                           float* __restrict__ out) {
    const int row = blockIdx.x;
    const int tid = threadIdx.x;
    const float4 v = reinterpret_cast<const float4*>(A + (size_t)row * DIM)[tid];
    float s = v.x * v.x + v.y * v.y + v.z * v.z + v.w * v.w;
    union { uint2 u; __nv_bfloat162 h[2]; } w;
    w.h[0] = __floats2bfloat162_rn(v.x, v.y);
    w.h[1] = __floats2bfloat162_rn(v.z, v.w);
    reinterpret_cast<uint2*>(Ab + (size_t)row * DIM)[tid] = w.u;
#pragma unroll
    for (int off = 16; off > 0; off >>= 1) s += __shfl_down_sync(0xffffffffu, s, off);
    __shared__ float ws[4];
    if ((tid & 31) == 0) ws[tid >> 5] = s;
    __syncthreads();
    if (tid == 0) out[row] = ws[0] + ws[1] + ws[2] + ws[3];
}

// plain fp32 -> bf16 convert (1 block / row of DIM, 128 thr)
__global__ void conv_only(const float* __restrict__ A, __nv_bfloat16* __restrict__ Ab) {
    const int row = blockIdx.x;
    const int tid = threadIdx.x;
    const float4 v = reinterpret_cast<const float4*>(A + (size_t)row * DIM)[tid];
    union { uint2 u; __nv_bfloat162 h[2]; } w;
    w.h[0] = __floats2bfloat162_rn(v.x, v.y);
    w.h[1] = __floats2bfloat162_rn(v.z, v.w);
    reinterpret_cast<uint2*>(Ab + (size_t)row * DIM)[tid] = w.u;
}

// cvec[d] = b_o[d] + dot(w_o[d,:], b_v)   (1 block / d, 128 thr)
__global__ void cvec_kernel(const float* __restrict__ w_o, const float* __restrict__ b_v,
                            const float* __restrict__ b_o, float* __restrict__ cvec) {
    const int d = blockIdx.x;
    const int tid = threadIdx.x;
    float s = 0.f;
#pragma unroll
    for (int i = tid; i < DIM; i += 128) s += w_o[(size_t)d * DIM + i] * b_v[i];
#pragma unroll
    for (int off = 16; off > 0; off >>= 1) s += __shfl_down_sync(0xffffffffu, s, off);
    __shared__ float ws[4];
    if ((tid & 31) == 0) ws[tid >> 5] = s;
    __syncthreads();
    if (tid == 0) cvec[d] = b_o[d] + ws[0] + ws[1] + ws[2] + ws[3];
}

// ---------------------------------------------------------------------------
// row softmax over 4096 bf16, in place (fp32 math), 1 block / row, 256 thr
// ---------------------------------------------------------------------------
__global__ __launch_bounds__(256) void softmax_bf16(__nv_bfloat16* __restrict__ data) {
    const int row = blockIdx.x;
    const int tid = threadIdx.x;
    uint4* p = reinterpret_cast<uint4*>(data + (size_t)row * NNEUR);
    uint4 a = p[tid], b = p[tid + 256];
    float f[16];
    const __nv_bfloat162* ha = reinterpret_cast<const __nv_bfloat162*>(&a);
    const __nv_bfloat162* hb = reinterpret_cast<const __nv_bfloat162*>(&b);
#pragma unroll
    for (int i = 0; i < 4; i++) {
        float2 u = __bfloat1622float2(ha[i]);
        f[2 * i] = u.x; f[2 * i + 1] = u.y;
        float2 w = __bfloat1622float2(hb[i]);
        f[8 + 2 * i] = w.x; f[8 + 2 * i + 1] = w.y;
    }
    float mx = f[0];
#pragma unroll
    for (int i = 1; i < 16; i++) mx = fmaxf(mx, f[i]);
    __shared__ float red[8];
#pragma unroll
    for (int off = 16; off > 0; off >>= 1)
        mx = fmaxf(mx, __shfl_xor_sync(0xffffffffu, mx, off));
    if ((tid & 31) == 0) red[tid >> 5] = mx;
    __syncthreads();
    mx = red[0];
#pragma unroll
    for (int w = 1; w < 8; w++) mx = fmaxf(mx, red[w]);

    float s = 0.f;
#pragma unroll
    for (int i = 0; i < 16; i++) { f[i] = __expf(f[i] - mx); s += f[i]; }
#pragma unroll
    for (int off = 16; off > 0; off >>= 1) s += __shfl_xor_sync(0xffffffffu, s, off);
    __syncthreads();
    if ((tid & 31) == 0) red[tid >> 5] = s;
    __syncthreads();
    s = red[0] + red[1] + red[2] + red[3] + red[4] + red[5] + red[6] + red[7];
    const float inv = 1.0f / s;

    __nv_bfloat162* oa = reinterpret_cast<__nv_bfloat162*>(&a);
    __nv_bfloat162* ob = reinterpret_cast<__nv_bfloat162*>(&b);
#pragma unroll
    for (int i = 0; i < 4; i++) {
        oa[i] = __floats2bfloat162_rn(f[2 * i] * inv, f[2 * i + 1] * inv);
        ob[i] = __floats2bfloat162_rn(f[8 + 2 * i] * inv, f[8 + 2 * i + 1] * inv);
    }
    p[tid] = a;
    p[tid + 256] = b;
}

// ---------------------------------------------------------------------------
extern "C" void kernel_launch(void* const* d_in, const int* in_sizes, int n_in,
                              void* d_out, int out_size)
{
    const float* x     = (const float*)d_in[0];
    const float* pos   = (const float*)d_in[1];
    const float* scale = (const float*)d_in[2];
    const float* w_v   = (const float*)d_in[3];
    const float* b_v   = (const float*)d_in[4];
    const float* w_o   = (const float*)d_in[5];
    const float* b_o   = (const float*)d_in[6];
    float* out = (float*)d_out;

    static float* pp2 = nullptr;
    static float *px2, *pcv;
    static __nv_bfloat16 *pxb, *ppb, *pwvb, *pwob, *pvalb, *pw2b, *pattn;
    if (pp2 == nullptr) {
        cudaGetSymbolAddress((void**)&pp2,   g_p2);
        cudaGetSymbolAddress((void**)&px2,   g_x2);
        cudaGetSymbolAddress((void**)&pcv,   g_cvec);
        cudaGetSymbolAddress((void**)&pxb,   g_xb);
        cudaGetSymbolAddress((void**)&ppb,   g_pb);
        cudaGetSymbolAddress((void**)&pwvb,  g_wvb);
        cudaGetSymbolAddress((void**)&pwob,  g_wob);
        cudaGetSymbolAddress((void**)&pvalb, g_valb);
        cudaGetSymbolAddress((void**)&pw2b,  g_w2b);
        cudaGetSymbolAddress((void**)&pattn, g_attn);
        cudaFuncSetAttribute(mma_gemm<1>, cudaFuncAttributeMaxDynamicSharedMemorySize, MG_SMEM);
        cudaFuncSetAttribute(mma_gemm<2>, cudaFuncAttributeMaxDynamicSharedMemorySize, MG_SMEM);
        cudaFuncSetAttribute(mma_gemm<3>, cudaFuncAttributeMaxDynamicSharedMemorySize, MG_SMEM);
    }

    // converts + norms
    conv_rowsq<<<BT,    128>>>(x,   pxb, px2);
    conv_rowsq<<<NNEUR, 128>>>(pos, ppb, pp2);
    conv_only <<<DIM,   128>>>(w_v, pwvb);
    conv_only <<<DIM,   128>>>(w_o, pwob);
    cvec_kernel<<<DIM,  128>>>(w_o, b_v, b_o, pcv);

    // values = pos @ w_v^T           (4096 x 512, K=512, bf16 out)
    mma_gemm<2><<<dim3(DIM / 128, NNEUR / 128), 256, MG_SMEM>>>(
        ppb, pwvb, pvalb, DIM, DIM, DIM, DIM / 32, nullptr, nullptr, nullptr);

    // W2^T = w_o @ values^T          (512 x 4096, K=512, bf16 out)
    mma_gemm<2><<<dim3(NNEUR / 128, DIM / 128), 256, MG_SMEM>>>(
        pwob, pvalb, pw2b, DIM, DIM, NNEUR, DIM / 32, nullptr, nullptr, nullptr);

    // interactions = f(x @ pos^T)    (8192 x 4096, K=512, fused epilogue -> bf16)
    mma_gemm<1><<<dim3(NNEUR / 128, BT / 128), 256, MG_SMEM>>>(
        pxb, ppb, pattn, DIM, DIM, NNEUR, DIM / 32, px2, pp2, scale);

    // softmax over neurons (bf16 in/out, fp32 math)
    softmax_bf16<<<BT, 256>>>(pattn);

    // out = attn @ W2 + cvec         (8192 x 512, K=4096, fp32 out, bias epi)
    mma_gemm<3><<<dim3(DIM / 128, BT / 128), 256, MG_SMEM>>>(
        pattn, pw2b, out, NNEUR, NNEUR, DIM, NNEUR / 32, nullptr, nullptr, pcv);
}